// round 5
// baseline (speedup 1.0000x reference)
#include <cuda_runtime.h>
#include <cuda_fp16.h>
#include <cstdint>

// GPTQLinear: out[M,N] = x[M,K] @ dequant(W)[N,K]^T + bias
// M=8192, K=4096, N=4096, GROUPSIZE=64.
// tcgen05 unavailable (harness compiles through compute_100 virtual arch ->
// ptxas target sm_100, no 'a' feature set). Classic tensor-core path:
// prepass to fp16 scratch, then multistage cp.async + ldmatrix +
// mma.sync.m16n8k16 GEMM with fp32 accumulate.

#define M_DIM 8192
#define K_DIM 4096
#define N_DIM 4096

__device__ __align__(256) __half g_xh[(size_t)M_DIM * K_DIM];   // 64 MB
__device__ __align__(256) __half g_wh[(size_t)N_DIM * K_DIM];   // 32 MB

// ---------------------------------------------------------------------------
__device__ __forceinline__ uint32_t smem_u32(const void* p) {
    uint32_t a;
    asm("{ .reg .u64 t; cvta.to.shared.u64 t, %1; cvt.u32.u64 %0, t; }"
        : "=r"(a) : "l"(p));
    return a;
}

#define LDSM4(R, addr)                                                        \
    asm volatile("ldmatrix.sync.aligned.m8n8.x4.shared.b16 {%0,%1,%2,%3}, [%4];" \
                 : "=r"((R)[0]), "=r"((R)[1]), "=r"((R)[2]), "=r"((R)[3])     \
                 : "r"(addr))

#define MMA16816(C, A, B0, B1)                                                \
    asm volatile("mma.sync.aligned.m16n8k16.row.col.f32.f16.f16.f32 "         \
                 "{%0,%1,%2,%3}, {%4,%5,%6,%7}, {%8,%9}, {%0,%1,%2,%3};"      \
                 : "+f"((C)[0]), "+f"((C)[1]), "+f"((C)[2]), "+f"((C)[3])     \
                 : "r"((A)[0]), "r"((A)[1]), "r"((A)[2]), "r"((A)[3]),        \
                   "r"(B0), "r"(B1))

// ---------------------------------------------------------------------------
// Kernel 1: x fp32 -> fp16
// ---------------------------------------------------------------------------
__global__ void k_convert_x(const float* __restrict__ x) {
    size_t i = ((size_t)blockIdx.x * 256 + threadIdx.x) * 8;
    float4 a = *reinterpret_cast<const float4*>(x + i);
    float4 b = *reinterpret_cast<const float4*>(x + i + 4);
    union { __half2 h[4]; uint4 u; } o;
    o.h[0] = __floats2half2_rn(a.x, a.y);
    o.h[1] = __floats2half2_rn(a.z, a.w);
    o.h[2] = __floats2half2_rn(b.x, b.y);
    o.h[3] = __floats2half2_rn(b.z, b.w);
    *reinterpret_cast<uint4*>(g_xh + i) = o.u;
}

// ---------------------------------------------------------------------------
// Kernel 2: dequant W -> fp16. packed_weight: int32[N, K/2], one byte per
// int32; low nibble = even k, high nibble = odd k.
// ---------------------------------------------------------------------------
__global__ void k_dequant_w(const int* __restrict__ pw,
                            const float* __restrict__ scales,
                            const float* __restrict__ zeros) {
    size_t t = (size_t)blockIdx.x * 256 + threadIdx.x;   // [0, N*K/8)
    int n  = (int)(t >> 9);                              // 512 threads per row
    int kk = ((int)t & 511) * 8;
    int g  = kk >> 6;
    float s = scales[n * 64 + g];
    float b = -zeros[n * 64 + g] * s;                    // w = q*s + b
    int4 p = *reinterpret_cast<const int4*>(pw + (size_t)n * (K_DIM / 2) + (kk >> 1));
    union { __half2 h[4]; uint4 u; } o;
    int v;
    v = p.x; o.h[0] = __floats2half2_rn(fmaf((float)(v & 15), s, b),
                                        fmaf((float)((v >> 4) & 15), s, b));
    v = p.y; o.h[1] = __floats2half2_rn(fmaf((float)(v & 15), s, b),
                                        fmaf((float)((v >> 4) & 15), s, b));
    v = p.z; o.h[2] = __floats2half2_rn(fmaf((float)(v & 15), s, b),
                                        fmaf((float)((v >> 4) & 15), s, b));
    v = p.w; o.h[3] = __floats2half2_rn(fmaf((float)(v & 15), s, b),
                                        fmaf((float)((v >> 4) & 15), s, b));
    *reinterpret_cast<uint4*>(g_wh + (size_t)n * K_DIM + kk) = o.u;
}

// ---------------------------------------------------------------------------
// Kernel 3: GEMM. CTA 128x128, BK=32, 4-stage cp.async, 8 warps of 64x32.
// smem tile: 64 B per row (32 halfs), 16B-seg swizzle seg ^= (row>>1)&3.
// ---------------------------------------------------------------------------
#define BM 128
#define BN 128
#define BK 32
#define A_TILE_B  (BM * 64)              // 8 KB
#define STAGE_B   (2 * A_TILE_B)         // 16 KB (A then B)
#define N_STAGES  4
#define SMEM_BYTES (N_STAGES * STAGE_B)  // 64 KB
#define NK (K_DIM / BK)                  // 128

#define LOAD_CHUNK(s, kc) do {                                                 \
    const uint32_t sa_ = sb + (uint32_t)(s) * STAGE_B;                         \
    const int ko_ = (kc) * BK;                                                 \
    _Pragma("unroll")                                                          \
    for (int i_ = 0; i_ < 2; i_++)                                             \
        asm volatile("cp.async.cg.shared.global [%0], [%1], 16;"               \
                     :: "r"(sa_ + a_dst[i_]), "l"(a_src[i_] + ko_) : "memory");\
    _Pragma("unroll")                                                          \
    for (int i_ = 0; i_ < 2; i_++)                                             \
        asm volatile("cp.async.cg.shared.global [%0], [%1], 16;"               \
                     :: "r"(sa_ + A_TILE_B + b_dst[i_]), "l"(b_src[i_] + ko_)  \
                     : "memory");                                              \
    asm volatile("cp.async.commit_group;" ::: "memory");                       \
} while (0)

__global__ void __launch_bounds__(256, 2)
k_gemm(const float* __restrict__ bias, float* __restrict__ out) {
    extern __shared__ char smem[];
    const uint32_t sb = smem_u32(smem);
    const int tid = threadIdx.x;
    const int wid = tid >> 5;
    const int lid = tid & 31;
    const int n0 = (int)(blockIdx.x & 31) * BN;    // N fastest: W stays in L2
    const int m0 = (int)(blockIdx.x >> 5) * BM;

    // ---- cp.async slots: per stage A = 512 16B segs, B = 512 ----
    const __half* a_src[2]; uint32_t a_dst[2];
    const __half* b_src[2]; uint32_t b_dst[2];
    {
        const __half* ab  = g_xh + (size_t)m0 * K_DIM;
        const __half* bbp = g_wh + (size_t)n0 * K_DIM;
        #pragma unroll
        for (int i = 0; i < 2; i++) {
            int q = tid + i * 256;
            int r = q >> 2, seg = q & 3;
            uint32_t sw = (uint32_t)(r * 64 + ((seg ^ ((r >> 1) & 3)) << 4));
            a_dst[i] = sw;  a_src[i] = ab  + (size_t)r * K_DIM + seg * 8;
            b_dst[i] = sw;  b_src[i] = bbp + (size_t)r * K_DIM + seg * 8;
        }
    }

    // ---- ldmatrix addresses (relative to stage base) ----
    // Warp tile: wm in {0,1} -> 64 M-rows, wn in {0..3} -> 32 N-cols.
    const int wm = wid & 1;
    const int wn = wid >> 1;
    uint32_t a_off[4][2];   // [mt][s16]
    #pragma unroll
    for (int mt = 0; mt < 4; mt++) {
        int r = wm * 64 + mt * 16 + (lid & 15);
        #pragma unroll
        for (int s16 = 0; s16 < 2; s16++) {
            int seg = s16 * 2 + (lid >> 4);
            a_off[mt][s16] = (uint32_t)(r * 64 + ((seg ^ ((r >> 1) & 3)) << 4));
        }
    }
    uint32_t b_off[2][2];   // [nt2][s16]; nt2 covers 16 N-cols
    #pragma unroll
    for (int nt2 = 0; nt2 < 2; nt2++) {
        int n = wn * 32 + nt2 * 16 + (lid & 7) + ((lid >> 4) << 3);
        #pragma unroll
        for (int s16 = 0; s16 < 2; s16++) {
            int seg = s16 * 2 + ((lid >> 3) & 1);
            b_off[nt2][s16] = (uint32_t)(A_TILE_B + n * 64
                                         + ((seg ^ ((n >> 1) & 3)) << 4));
        }
    }

    float c[4][4][4];
    #pragma unroll
    for (int mt = 0; mt < 4; mt++)
        #pragma unroll
        for (int nt = 0; nt < 4; nt++)
            #pragma unroll
            for (int j = 0; j < 4; j++) c[mt][nt][j] = 0.0f;

    LOAD_CHUNK(0, 0);
    LOAD_CHUNK(1, 1);
    LOAD_CHUNK(2, 2);

    for (int kc = 0; kc < NK; ++kc) {
        // chunk kc ready? committed groups reach kc+2 while kc <= NK-3.
        if (kc < NK - 2)       asm volatile("cp.async.wait_group 2;" ::: "memory");
        else if (kc == NK - 2) asm volatile("cp.async.wait_group 1;" ::: "memory");
        else                   asm volatile("cp.async.wait_group 0;" ::: "memory");
        __syncthreads();

        // refill: stage (kc+3)%4 held chunk kc-1, fully consumed before the
        // barrier above.
        if (kc + 3 < NK) LOAD_CHUNK((kc + 3) & 3, kc + 3);

        const uint32_t st = sb + (uint32_t)(kc & 3) * STAGE_B;
        #pragma unroll
        for (int s16 = 0; s16 < 2; s16++) {
            uint32_t a[4][4], b[2][4];
            #pragma unroll
            for (int mt = 0; mt < 4; mt++) LDSM4(a[mt], st + a_off[mt][s16]);
            #pragma unroll
            for (int nt2 = 0; nt2 < 2; nt2++) LDSM4(b[nt2], st + b_off[nt2][s16]);
            #pragma unroll
            for (int mt = 0; mt < 4; mt++) {
                MMA16816(c[mt][0], a[mt], b[0][0], b[0][1]);
                MMA16816(c[mt][1], a[mt], b[0][2], b[0][3]);
                MMA16816(c[mt][2], a[mt], b[1][0], b[1][1]);
                MMA16816(c[mt][3], a[mt], b[1][2], b[1][3]);
            }
        }
    }

    // ---- epilogue: fragment (m16n8): c0,c1 -> (g2, t2..t2+1), c2,c3 -> g2+8
    const int g2 = lid >> 2;
    const int t2 = (lid & 3) << 1;
    #pragma unroll
    for (int mt = 0; mt < 4; mt++) {
        int m = m0 + wm * 64 + mt * 16 + g2;
        float* r0 = out + (size_t)m * N_DIM       + n0 + wn * 32 + t2;
        float* r1 = out + (size_t)(m + 8) * N_DIM + n0 + wn * 32 + t2;
        #pragma unroll
        for (int nt = 0; nt < 4; nt++) {
            float2 bv = *reinterpret_cast<const float2*>(
                bias + n0 + wn * 32 + nt * 8 + t2);
            float2 v0 = { c[mt][nt][0] + bv.x, c[mt][nt][1] + bv.y };
            float2 v1 = { c[mt][nt][2] + bv.x, c[mt][nt][3] + bv.y };
            *reinterpret_cast<float2*>(r0 + nt * 8) = v0;
            *reinterpret_cast<float2*>(r1 + nt * 8) = v1;
        }
    }
}

// ---------------------------------------------------------------------------
extern "C" void kernel_launch(void* const* d_in, const int* in_sizes, int n_in,
                              void* d_out, int out_size) {
    const float* x      = (const float*)d_in[0];
    const int*   pw     = (const int*)d_in[1];
    const float* scales = (const float*)d_in[2];
    const float* zeros  = (const float*)d_in[3];
    const float* bias   = (const float*)d_in[4];
    float* out = (float*)d_out;

    cudaFuncSetAttribute(k_gemm, cudaFuncAttributeMaxDynamicSharedMemorySize,
                         SMEM_BYTES);

    k_convert_x<<<(int)(((size_t)M_DIM * K_DIM / 8) / 256), 256>>>(x);
    k_dequant_w<<<(int)(((size_t)N_DIM * K_DIM / 8) / 256), 256>>>(pw, scales, zeros);
    k_gemm<<<(M_DIM / BM) * (N_DIM / BN), 256, SMEM_BYTES>>>(bias, out);
}